// round 2
// baseline (speedup 1.0000x reference)
#include <cuda_runtime.h>
#include <math.h>

#define NMAX 50000
#define EMAX 500000

// ---------------- scratch (static device globals: no allocation allowed) ----
__device__ float g_XN[NMAX * 128];
__device__ float g_Q[NMAX * 128];
__device__ float g_K[NMAX * 128];
__device__ float g_V[NMAX * 128];
__device__ float g_LOG[EMAX * 8];
__device__ float g_M[NMAX * 8];
__device__ float g_S[NMAX * 8];
__device__ float g_AGG[NMAX * 128];
__device__ float g_XMID[NMAX * 128];
__device__ float g_FFNH[NMAX * 256];

__device__ __forceinline__ float gelu_f(float x) {
    return 0.5f * x * (1.0f + erff(x * 0.70710678118654752f));
}

// ---------------- LayerNorm: one warp per row of 128 ------------------------
__global__ void ln_kernel(const float* __restrict__ X, const float* __restrict__ G,
                          const float* __restrict__ B, float* __restrict__ O, int Nrows) {
    int warp = (blockIdx.x * blockDim.x + threadIdx.x) >> 5;
    int lane = threadIdx.x & 31;
    if (warp >= Nrows) return;
    const float* xp = X + (size_t)warp * 128;
    float4 v = *(const float4*)(xp + lane * 4);
    float s = v.x + v.y + v.z + v.w;
    #pragma unroll
    for (int o = 16; o; o >>= 1) s += __shfl_xor_sync(0xffffffffu, s, o);
    float mean = s * (1.0f / 128.0f);
    float d0 = v.x - mean, d1 = v.y - mean, d2 = v.z - mean, d3 = v.w - mean;
    float ss = d0 * d0 + d1 * d1 + d2 * d2 + d3 * d3;
    #pragma unroll
    for (int o = 16; o; o >>= 1) ss += __shfl_xor_sync(0xffffffffu, ss, o);
    float inv = rsqrtf(ss * (1.0f / 128.0f) + 1e-5f);
    float* op = O + (size_t)warp * 128;
    int c = lane * 4;
    op[c + 0] = d0 * inv * G[c + 0] + B[c + 0];
    op[c + 1] = d1 * inv * G[c + 1] + B[c + 1];
    op[c + 2] = d2 * inv * G[c + 2] + B[c + 2];
    op[c + 3] = d3 * inv * G[c + 3] + B[c + 3];
}

// ---------------- generic fp32 GEMM, 64x64x16 tiles, fused epilogues --------
// mode 0: C = A@B + bias
// mode 1: C = gelu(A@B + bias)
// mode 2: C = res + A@B + bias
// mode 3: C = res + gam*(A@B + bias) + bet   (gam/bet are [M,N] elementwise)
__global__ void gemm_kernel(const float* __restrict__ A, const float* __restrict__ B,
                            const float* __restrict__ bias, const float* __restrict__ res,
                            const float* __restrict__ gam, const float* __restrict__ bet,
                            float* __restrict__ C, int M, int N, int K, int mode) {
    __shared__ float As[16][65];
    __shared__ float Bs[16][68];
    const int tid = threadIdx.x;
    const int tx = tid & 15, ty = tid >> 4;
    const int row0 = blockIdx.y * 64, col0 = blockIdx.x * 64;
    float acc[4][4] = {};
    const int lm = tid >> 2, lk = (tid & 3) << 2;
    const int lkb = tid >> 4, lnb = (tid & 15) << 2;
    for (int kt = 0; kt < K; kt += 16) {
        int ar = row0 + lm;
        float4 av = make_float4(0.f, 0.f, 0.f, 0.f);
        if (ar < M) av = *(const float4*)(A + (size_t)ar * K + kt + lk);
        As[lk + 0][lm] = av.x; As[lk + 1][lm] = av.y;
        As[lk + 2][lm] = av.z; As[lk + 3][lm] = av.w;
        float4 bv = *(const float4*)(B + (size_t)(kt + lkb) * N + col0 + lnb);
        Bs[lkb][lnb + 0] = bv.x; Bs[lkb][lnb + 1] = bv.y;
        Bs[lkb][lnb + 2] = bv.z; Bs[lkb][lnb + 3] = bv.w;
        __syncthreads();
        #pragma unroll
        for (int k = 0; k < 16; k++) {
            float a[4], b[4];
            #pragma unroll
            for (int i = 0; i < 4; i++) a[i] = As[k][(ty << 2) + i];
            #pragma unroll
            for (int j = 0; j < 4; j++) b[j] = Bs[k][(tx << 2) + j];
            #pragma unroll
            for (int i = 0; i < 4; i++)
                #pragma unroll
                for (int j = 0; j < 4; j++) acc[i][j] = fmaf(a[i], b[j], acc[i][j]);
        }
        __syncthreads();
    }
    #pragma unroll
    for (int i = 0; i < 4; i++) {
        int r = row0 + (ty << 2) + i;
        if (r >= M) continue;
        #pragma unroll
        for (int j = 0; j < 4; j++) {
            int c = col0 + (tx << 2) + j;
            float v = acc[i][j] + (bias ? bias[c] : 0.0f);
            size_t idx = (size_t)r * N + c;
            if (mode == 1) v = gelu_f(v);
            else if (mode == 2) v += res[idx];
            else if (mode == 3) v = res[idx] + gam[idx] * v + bet[idx];
            C[idx] = v;
        }
    }
}

// ---------------- edge pass A: logits = QK/4 + ea-MLP; atomicMax into M -----
// 64 edges per block, 256 threads.
__global__ void edge_logits_kernel(const float* __restrict__ EA, const int* __restrict__ EI,
                                   const float* __restrict__ W1, const float* __restrict__ B1,
                                   const float* __restrict__ W2, const float* __restrict__ B2,
                                   const float* __restrict__ Q, const float* __restrict__ Kk,
                                   float* __restrict__ LOG, float* __restrict__ Mb, int E) {
    __shared__ float attr[64][33];
    __shared__ float w1s[32][65];
    __shared__ float ha[64][65];
    __shared__ float w2s[64][8];
    __shared__ float b2s[8];
    __shared__ int s_src[64], s_dst[64];
    const int tid = threadIdx.x;
    const int e0 = blockIdx.x * 64;
    for (int i = tid; i < 64 * 32; i += 256) {
        int e = i >> 5, f = i & 31;
        int ge = e0 + e;
        attr[e][f] = (ge < E) ? EA[(size_t)ge * 32 + f] : 0.0f;
    }
    for (int i = tid; i < 32 * 64; i += 256) w1s[i >> 6][i & 63] = W1[i];
    for (int i = tid; i < 64 * 8; i += 256) w2s[i >> 3][i & 7] = W2[i];
    if (tid < 8) b2s[tid] = B2[tid];
    if (tid < 64) {
        int ge = min(e0 + tid, E - 1);
        s_src[tid] = EI[ge];
        s_dst[tid] = EI[E + ge];
    }
    __syncthreads();
    // hidden = gelu(attr @ W1 + B1): 64x64, 4x4 per thread
    {
        const int tx = tid & 15, ty = tid >> 4;
        float acc[4][4] = {};
        for (int k = 0; k < 32; k++) {
            float a[4], b[4];
            #pragma unroll
            for (int i = 0; i < 4; i++) a[i] = attr[(ty << 2) + i][k];
            #pragma unroll
            for (int j = 0; j < 4; j++) b[j] = w1s[k][(tx << 2) + j];
            #pragma unroll
            for (int i = 0; i < 4; i++)
                #pragma unroll
                for (int j = 0; j < 4; j++) acc[i][j] = fmaf(a[i], b[j], acc[i][j]);
        }
        #pragma unroll
        for (int i = 0; i < 4; i++)
            #pragma unroll
            for (int j = 0; j < 4; j++)
                ha[(ty << 2) + i][(tx << 2) + j] =
                    gelu_f(acc[i][j] + __ldg(B1 + (tx << 2) + j));
    }
    __syncthreads();
    // logits per (edge, head)
    for (int i = tid; i < 512; i += 256) {
        int e = i >> 3, h = i & 7;
        int ge = e0 + e;
        if (ge >= E) continue;
        int dd = s_dst[e], sr = s_src[e];
        const float* qp = Q + (size_t)dd * 128 + h * 16;
        const float* kp = Kk + (size_t)sr * 128 + h * 16;
        float lg = 0.0f;
        #pragma unroll
        for (int d = 0; d < 16; d += 4) {
            float4 qv = *(const float4*)(qp + d);
            float4 kv = *(const float4*)(kp + d);
            lg += qv.x * kv.x + qv.y * kv.y + qv.z * kv.z + qv.w * kv.w;
        }
        lg *= 0.25f;
        float ea = b2s[h];
        #pragma unroll 8
        for (int k = 0; k < 64; k++) ea = fmaf(ha[e][k], w2s[k][h], ea);
        lg += ea;
        LOG[(size_t)ge * 8 + h] = lg;
        // m = max(segment_max, 0): M zero-init; only positive logits can raise it.
        // float ordering == int ordering for positive floats.
        if (lg > 0.0f) atomicMax((int*)Mb + (size_t)dd * 8 + h, __float_as_int(lg));
    }
}

// ---------------- edge pass B: ex = exp(l - m[dst]); atomicAdd into S -------
__global__ void edge_exp_kernel(const int* __restrict__ EI, float* __restrict__ LOG,
                                const float* __restrict__ Mb, float* __restrict__ S, int E) {
    int i = blockIdx.x * blockDim.x + threadIdx.x;
    if (i >= E * 8) return;
    int e = i >> 3, h = i & 7;
    int d = __ldg(EI + E + e);
    float ex = expf(LOG[i] - Mb[(size_t)d * 8 + h]);
    LOG[i] = ex;
    atomicAdd(&S[(size_t)d * 8 + h], ex);
}

// ---------------- edge pass C: gate MLP + attn * gate * V[src] scatter ------
// 32 edges per block, 256 threads (8 warps x 4 edges each).
__global__ void edge_agg_kernel(const float* __restrict__ EA, const int* __restrict__ EI,
                                const float* __restrict__ W1, const float* __restrict__ B1,
                                const float* __restrict__ W2, const float* __restrict__ B2,
                                const float* __restrict__ V, const float* __restrict__ LOG,
                                const float* __restrict__ S, float* __restrict__ AGG, int E) {
    __shared__ float attr[32][33];
    __shared__ float hg[32][65];
    __shared__ float w2s[64][128];
    __shared__ float attn_s[32][8];
    __shared__ float b2s[128];
    __shared__ int s_src[32], s_dst[32];
    const int tid = threadIdx.x;
    const int e0 = blockIdx.x * 32;
    for (int i = tid; i < 32 * 32; i += 256) {
        int e = i >> 5, f = i & 31;
        int ge = e0 + e;
        attr[e][f] = (ge < E) ? EA[(size_t)ge * 32 + f] : 0.0f;
    }
    for (int i = tid; i < 64 * 128; i += 256) w2s[i >> 7][i & 127] = W2[i];
    if (tid < 128) b2s[tid] = B2[tid];
    if (tid < 32) {
        int ge = min(e0 + tid, E - 1);
        s_src[tid] = EI[ge];
        s_dst[tid] = EI[E + ge];
    }
    {
        int e = tid >> 3, h = tid & 7;
        int ge = e0 + e;
        float a = 0.0f;
        if (ge < E) {
            int d = __ldg(EI + E + ge);
            a = LOG[(size_t)ge * 8 + h] / (S[(size_t)d * 8 + h] + 1e-10f);
        }
        attn_s[e][h] = a;
    }
    __syncthreads();
    // hidden_g = gelu(attr @ eg_w1 + b1): thread -> edge tid>>3, 8 hidden units
    {
        int e = tid >> 3;
        int hh0 = (tid & 7) << 3;
        float acc[8];
        #pragma unroll
        for (int j = 0; j < 8; j++) acc[j] = __ldg(B1 + hh0 + j);
        for (int k = 0; k < 32; k++) {
            float a = attr[e][k];
            const float* wr = W1 + k * 64 + hh0;
            #pragma unroll
            for (int j = 0; j < 8; j++) acc[j] = fmaf(a, __ldg(wr + j), acc[j]);
        }
        #pragma unroll
        for (int j = 0; j < 8; j++) hg[e][hh0 + j] = gelu_f(acc[j]);
    }
    __syncthreads();
    const int lane = tid & 31, w = tid >> 5;
    #pragma unroll
    for (int ei = 0; ei < 4; ei++) {
        int e = (w << 2) + ei;
        int ge = e0 + e;
        if (ge >= E) continue;
        int sr = s_src[e], ds = s_dst[e];
        int c = lane << 2;
        float g0 = b2s[c + 0], g1 = b2s[c + 1], g2 = b2s[c + 2], g3 = b2s[c + 3];
        #pragma unroll 8
        for (int k = 0; k < 64; k++) {
            float hv = hg[e][k];
            float4 wv = *(const float4*)&w2s[k][c];
            g0 = fmaf(hv, wv.x, g0);
            g1 = fmaf(hv, wv.y, g1);
            g2 = fmaf(hv, wv.z, g2);
            g3 = fmaf(hv, wv.w, g3);
        }
        g0 = 1.0f / (1.0f + expf(-g0));
        g1 = 1.0f / (1.0f + expf(-g1));
        g2 = 1.0f / (1.0f + expf(-g2));
        g3 = 1.0f / (1.0f + expf(-g3));
        float4 vv = *(const float4*)(V + (size_t)sr * 128 + c);
        float at = attn_s[e][lane >> 2];
        float* ap = AGG + (size_t)ds * 128 + c;
        atomicAdd(ap + 0, at * g0 * vv.x);
        atomicAdd(ap + 1, at * g1 * vv.y);
        atomicAdd(ap + 2, at * g2 * vv.z);
        atomicAdd(ap + 3, at * g3 * vv.w);
    }
}

// ---------------- launch --------------------------------------------------
extern "C" void kernel_launch(void* const* d_in, const int* in_sizes, int n_in,
                              void* d_out, int out_size) {
    const float* x      = (const float*)d_in[0];
    const float* ea     = (const float*)d_in[1];
    const float* gamma  = (const float*)d_in[2];
    const float* beta   = (const float*)d_in[3];
    const float* Wq     = (const float*)d_in[4];
    const float* Wk     = (const float*)d_in[5];
    const float* Wv     = (const float*)d_in[6];
    const float* Wo     = (const float*)d_in[7];
    const float* bo     = (const float*)d_in[8];
    const float* ea_w1  = (const float*)d_in[9];
    const float* ea_b1  = (const float*)d_in[10];
    const float* ea_w2  = (const float*)d_in[11];
    const float* ea_b2  = (const float*)d_in[12];
    const float* eg_w1  = (const float*)d_in[13];
    const float* eg_b1  = (const float*)d_in[14];
    const float* eg_w2  = (const float*)d_in[15];
    const float* eg_b2  = (const float*)d_in[16];
    const float* ln1_g  = (const float*)d_in[17];
    const float* ln1_b  = (const float*)d_in[18];
    const float* ln2_g  = (const float*)d_in[19];
    const float* ln2_b  = (const float*)d_in[20];
    const float* ffn_w1 = (const float*)d_in[21];
    const float* ffn_b1 = (const float*)d_in[22];
    const float* ffn_w2 = (const float*)d_in[23];
    const float* ffn_b2 = (const float*)d_in[24];
    const int*   ei     = (const int*)d_in[25];

    int N = in_sizes[0] / 128;
    int E = in_sizes[25] / 2;

    float *pXN, *pQ, *pK, *pV, *pLOG, *pM, *pS, *pAGG, *pXMID, *pFFNH;
    cudaGetSymbolAddress((void**)&pXN, g_XN);
    cudaGetSymbolAddress((void**)&pQ, g_Q);
    cudaGetSymbolAddress((void**)&pK, g_K);
    cudaGetSymbolAddress((void**)&pV, g_V);
    cudaGetSymbolAddress((void**)&pLOG, g_LOG);
    cudaGetSymbolAddress((void**)&pM, g_M);
    cudaGetSymbolAddress((void**)&pS, g_S);
    cudaGetSymbolAddress((void**)&pAGG, g_AGG);
    cudaGetSymbolAddress((void**)&pXMID, g_XMID);
    cudaGetSymbolAddress((void**)&pFFNH, g_FFNH);

    cudaMemsetAsync(pM, 0, (size_t)N * 8 * sizeof(float));
    cudaMemsetAsync(pS, 0, (size_t)N * 8 * sizeof(float));
    cudaMemsetAsync(pAGG, 0, (size_t)N * 128 * sizeof(float));

    int lnBlocks = (N * 32 + 255) / 256;
    ln_kernel<<<lnBlocks, 256>>>(x, ln1_g, ln1_b, pXN, N);

    dim3 g128(2, (N + 63) / 64);
    gemm_kernel<<<g128, 256>>>(pXN, Wq, nullptr, nullptr, nullptr, nullptr, pQ, N, 128, 128, 0);
    gemm_kernel<<<g128, 256>>>(pXN, Wk, nullptr, nullptr, nullptr, nullptr, pK, N, 128, 128, 0);
    gemm_kernel<<<g128, 256>>>(pXN, Wv, nullptr, nullptr, nullptr, nullptr, pV, N, 128, 128, 0);

    edge_logits_kernel<<<(E + 63) / 64, 256>>>(ea, ei, ea_w1, ea_b1, ea_w2, ea_b2,
                                               pQ, pK, pLOG, pM, E);
    edge_exp_kernel<<<(E * 8 + 255) / 256, 256>>>(ei, pLOG, pM, pS, E);
    edge_agg_kernel<<<(E + 31) / 32, 256>>>(ea, ei, eg_w1, eg_b1, eg_w2, eg_b2,
                                            pV, pLOG, pS, pAGG, E);

    // XMID = x + gamma*(AGG@Wo + bo) + beta
    gemm_kernel<<<g128, 256>>>(pAGG, Wo, bo, x, gamma, beta, pXMID, N, 128, 128, 3);
    // x2 = LN2(XMID) (reuse XN buffer)
    ln_kernel<<<lnBlocks, 256>>>(pXMID, ln2_g, ln2_b, pXN, N);
    // FFNH = gelu(x2 @ ffn_w1 + b1)
    dim3 g256(4, (N + 63) / 64);
    gemm_kernel<<<g256, 256>>>(pXN, ffn_w1, ffn_b1, nullptr, nullptr, nullptr, pFFNH, N, 256, 128, 1);
    // out = XMID + FFNH @ ffn_w2 + b2
    gemm_kernel<<<g128, 256>>>(pFFNH, ffn_w2, ffn_b2, pXMID, nullptr, nullptr,
                               (float*)d_out, N, 128, 256, 2);
}

// round 3
// speedup vs baseline: 1.2663x; 1.2663x over previous
#include <cuda_runtime.h>
#include <math.h>

#define NMAX 50000
#define EMAX 500000

// ---------------- static scratch ------------------------------------------
__device__ float g_XN[NMAX * 128];
__device__ float g_Q[NMAX * 128];
__device__ float g_K[NMAX * 128];
__device__ float g_V[NMAX * 128];
__device__ float g_AGG[NMAX * 128];
__device__ float g_XMID[NMAX * 128];
__device__ float g_FFNH[NMAX * 256];
__device__ float g_HE[EMAX * 64];      // hidden of edge MLPs (HA, then reused for HG)
__device__ float g_LOG[EMAX * 8];      // logits, sorted-edge order
__device__ float g_ATT[EMAX * 8];      // attention weights, sorted-edge order
__device__ float g_WS[EMAX * 128];     // weighted edge contributions, sorted order
__device__ int   g_perm[EMAX];
__device__ int   g_srcs[EMAX];
__device__ int   g_dsts[EMAX];
__device__ int   g_cnt[NMAX];
__device__ int   g_rowstart[NMAX + 1];
__device__ int   g_cursor[NMAX];
__device__ int   g_bsum[256];
__device__ int   g_bsumex[256];

__device__ __forceinline__ float gelu_f(float x) {
    return 0.5f * x * (1.0f + erff(x * 0.70710678118654752f));
}

// ---------------- LayerNorm: one warp per row of 128 ------------------------
__global__ void ln_kernel(const float* __restrict__ X, const float* __restrict__ G,
                          const float* __restrict__ B, float* __restrict__ O, int Nrows) {
    int warp = (blockIdx.x * blockDim.x + threadIdx.x) >> 5;
    int lane = threadIdx.x & 31;
    if (warp >= Nrows) return;
    const float* xp = X + (size_t)warp * 128;
    float4 v = *(const float4*)(xp + lane * 4);
    float s = v.x + v.y + v.z + v.w;
    #pragma unroll
    for (int o = 16; o; o >>= 1) s += __shfl_xor_sync(0xffffffffu, s, o);
    float mean = s * (1.0f / 128.0f);
    float d0 = v.x - mean, d1 = v.y - mean, d2 = v.z - mean, d3 = v.w - mean;
    float ss = d0 * d0 + d1 * d1 + d2 * d2 + d3 * d3;
    #pragma unroll
    for (int o = 16; o; o >>= 1) ss += __shfl_xor_sync(0xffffffffu, ss, o);
    float inv = rsqrtf(ss * (1.0f / 128.0f) + 1e-5f);
    float* op = O + (size_t)warp * 128;
    int c = lane * 4;
    op[c + 0] = d0 * inv * G[c + 0] + B[c + 0];
    op[c + 1] = d1 * inv * G[c + 1] + B[c + 1];
    op[c + 2] = d2 * inv * G[c + 2] + B[c + 2];
    op[c + 3] = d3 * inv * G[c + 3] + B[c + 3];
}

// ---------------- generic fp32 GEMM, 64x64x16 tiles, fused epilogues --------
// mode 0: C = A@B + bias
// mode 1: C = gelu(A@B + bias)
// mode 2: C = res + A@B + bias
// mode 3: C = res + gam*(A@B + bias) + bet
// rowidx: optional A-row gather (A row of logical row r is rowidx[r])
__global__ void gemm_kernel(const float* __restrict__ A, const float* __restrict__ B,
                            const float* __restrict__ bias, const float* __restrict__ res,
                            const float* __restrict__ gam, const float* __restrict__ bet,
                            float* __restrict__ C, int M, int N, int K, int mode,
                            const int* __restrict__ rowidx) {
    __shared__ float As[16][65];
    __shared__ float Bs[16][68];
    const int tid = threadIdx.x;
    const int tx = tid & 15, ty = tid >> 4;
    const int row0 = blockIdx.y * 64, col0 = blockIdx.x * 64;
    float acc[4][4] = {};
    const int lm = tid >> 2, lk = (tid & 3) << 2;
    const int lkb = tid >> 4, lnb = (tid & 15) << 2;
    for (int kt = 0; kt < K; kt += 16) {
        int ar = row0 + lm;
        float4 av = make_float4(0.f, 0.f, 0.f, 0.f);
        if (ar < M) {
            int pr = rowidx ? rowidx[ar] : ar;
            av = *(const float4*)(A + (size_t)pr * K + kt + lk);
        }
        As[lk + 0][lm] = av.x; As[lk + 1][lm] = av.y;
        As[lk + 2][lm] = av.z; As[lk + 3][lm] = av.w;
        float4 bv = *(const float4*)(B + (size_t)(kt + lkb) * N + col0 + lnb);
        Bs[lkb][lnb + 0] = bv.x; Bs[lkb][lnb + 1] = bv.y;
        Bs[lkb][lnb + 2] = bv.z; Bs[lkb][lnb + 3] = bv.w;
        __syncthreads();
        #pragma unroll
        for (int k = 0; k < 16; k++) {
            float a[4], b[4];
            #pragma unroll
            for (int i = 0; i < 4; i++) a[i] = As[k][(ty << 2) + i];
            #pragma unroll
            for (int j = 0; j < 4; j++) b[j] = Bs[k][(tx << 2) + j];
            #pragma unroll
            for (int i = 0; i < 4; i++)
                #pragma unroll
                for (int j = 0; j < 4; j++) acc[i][j] = fmaf(a[i], b[j], acc[i][j]);
        }
        __syncthreads();
    }
    #pragma unroll
    for (int i = 0; i < 4; i++) {
        int r = row0 + (ty << 2) + i;
        if (r >= M) continue;
        #pragma unroll
        for (int j = 0; j < 4; j++) {
            int c = col0 + (tx << 2) + j;
            float v = acc[i][j] + (bias ? bias[c] : 0.0f);
            size_t idx = (size_t)r * N + c;
            if (mode == 1) v = gelu_f(v);
            else if (mode == 2) v += res[idx];
            else if (mode == 3) v = res[idx] + gam[idx] * v + bet[idx];
            C[idx] = v;
        }
    }
}

// ---------------- counting sort of edges by dst -----------------------------
__global__ void hist_kernel(const int* __restrict__ EI, int* __restrict__ cnt, int E) {
    int e = blockIdx.x * 256 + threadIdx.x;
    if (e < E) atomicAdd(&cnt[EI[E + e]], 1);
}

__global__ void scan1_kernel(const int* __restrict__ cnt, int* __restrict__ excl,
                             int* __restrict__ bsum, int N) {
    __shared__ int sm[256];
    int t = threadIdx.x, i = blockIdx.x * 256 + t;
    int v = (i < N) ? cnt[i] : 0;
    sm[t] = v; __syncthreads();
    for (int o = 1; o < 256; o <<= 1) {
        int a = (t >= o) ? sm[t - o] : 0;
        __syncthreads();
        sm[t] += a;
        __syncthreads();
    }
    if (i < N) excl[i] = sm[t] - v;
    if (t == 255) bsum[blockIdx.x] = sm[255];
}

__global__ void scan2_kernel(const int* __restrict__ bsum, int* __restrict__ bsumex, int nb) {
    __shared__ int sm[256];
    int t = threadIdx.x;
    int v = (t < nb) ? bsum[t] : 0;
    sm[t] = v; __syncthreads();
    for (int o = 1; o < 256; o <<= 1) {
        int a = (t >= o) ? sm[t - o] : 0;
        __syncthreads();
        sm[t] += a;
        __syncthreads();
    }
    bsumex[t] = sm[t] - v;
}

__global__ void scan3_kernel(int* __restrict__ rowstart, int* __restrict__ cursor,
                             const int* __restrict__ bsumex, int N, int E) {
    int i = blockIdx.x * 256 + threadIdx.x;
    if (i < N) {
        int v = rowstart[i] + bsumex[blockIdx.x];
        rowstart[i] = v;
        cursor[i] = v;
        if (i == N - 1) rowstart[N] = E;
    }
}

__global__ void scatter_kernel(const int* __restrict__ EI, int* __restrict__ cursor,
                               int* __restrict__ perm, int* __restrict__ srcs,
                               int* __restrict__ dsts, int E) {
    int e = blockIdx.x * 256 + threadIdx.x;
    if (e >= E) return;
    int d = EI[E + e];
    int pos = atomicAdd(&cursor[d], 1);
    perm[pos] = e;
    srcs[pos] = EI[e];
    dsts[pos] = d;
}

// ---------------- logits (sorted order): QK/4 + HA @ ea_w2 + b2 -------------
__global__ void logits_kernel(const float* __restrict__ HA, const int* __restrict__ srcs,
                              const int* __restrict__ dsts, const float* __restrict__ W2,
                              const float* __restrict__ B2, const float* __restrict__ Q,
                              const float* __restrict__ Kk, float* __restrict__ LOG, int E) {
    __shared__ float ha[64][65];
    __shared__ float w2[64][9];
    __shared__ float b2s[8];
    int tid = threadIdx.x;
    int i0 = blockIdx.x * 64;
    for (int i = tid; i < 64 * 64; i += 256) {
        int r = i >> 6, c = i & 63;
        int gi = i0 + r;
        ha[r][c] = (gi < E) ? HA[(size_t)gi * 64 + c] : 0.f;
    }
    for (int i = tid; i < 512; i += 256) w2[i >> 3][i & 7] = W2[i];
    if (tid < 8) b2s[tid] = B2[tid];
    __syncthreads();
    for (int i = tid; i < 512; i += 256) {
        int e = i >> 3, h = i & 7;
        int gi = i0 + e;
        if (gi >= E) continue;
        const float* qp = Q + (size_t)dsts[gi] * 128 + h * 16;
        const float* kp = Kk + (size_t)srcs[gi] * 128 + h * 16;
        float lg = 0.f;
        #pragma unroll
        for (int d = 0; d < 16; d += 4) {
            float4 qv = *(const float4*)(qp + d);
            float4 kv = *(const float4*)(kp + d);
            lg += qv.x * kv.x + qv.y * kv.y + qv.z * kv.z + qv.w * kv.w;
        }
        lg *= 0.25f;
        float a = b2s[h];
        #pragma unroll 8
        for (int k = 0; k < 64; k++) a = fmaf(ha[e][k], w2[k][h], a);
        LOG[(size_t)gi * 8 + h] = lg + a;
    }
}

// ---------------- per-node softmax (warp/node, max clamped at 0) ------------
__global__ void softmax_kernel(const float* __restrict__ LOG, const int* __restrict__ rowstart,
                               float* __restrict__ ATT, int N) {
    int warp = (blockIdx.x * blockDim.x + threadIdx.x) >> 5;
    int lane = threadIdx.x & 31;
    if (warp >= N) return;
    int s0 = rowstart[warp], s1 = rowstart[warp + 1];
    int eo = lane >> 3, h = lane & 7;
    float m = 0.0f;  // torch include_self max-with-0
    for (int i = s0 + eo; i < s1; i += 4) m = fmaxf(m, LOG[(size_t)i * 8 + h]);
    m = fmaxf(m, __shfl_xor_sync(0xffffffffu, m, 8));
    m = fmaxf(m, __shfl_xor_sync(0xffffffffu, m, 16));
    float s = 0.0f;
    for (int i = s0 + eo; i < s1; i += 4) s += expf(LOG[(size_t)i * 8 + h] - m);
    s += __shfl_xor_sync(0xffffffffu, s, 8);
    s += __shfl_xor_sync(0xffffffffu, s, 16);
    float inv = 1.0f / (s + 1e-10f);
    for (int i = s0 + eo; i < s1; i += 4)
        ATT[(size_t)i * 8 + h] = expf(LOG[(size_t)i * 8 + h] - m) * inv;
}

// ---------------- gate GEMM: WS = sigmoid(HG@W2+b2)*att*V[src] --------------
// A = HG (sorted, [E,64]), B = eg_w2 [64,128]
__global__ void gate_gemm_kernel(const float* __restrict__ A, const float* __restrict__ B,
                                 const float* __restrict__ bias, const float* __restrict__ V,
                                 const int* __restrict__ srcs, const float* __restrict__ ATT,
                                 float* __restrict__ WS, int M) {
    __shared__ float As[16][65];
    __shared__ float Bs[16][68];
    const int tid = threadIdx.x;
    const int tx = tid & 15, ty = tid >> 4;
    const int row0 = blockIdx.y * 64, col0 = blockIdx.x * 64;
    float acc[4][4] = {};
    const int lm = tid >> 2, lk = (tid & 3) << 2;
    const int lkb = tid >> 4, lnb = (tid & 15) << 2;
    for (int kt = 0; kt < 64; kt += 16) {
        int ar = row0 + lm;
        float4 av = make_float4(0.f, 0.f, 0.f, 0.f);
        if (ar < M) av = *(const float4*)(A + (size_t)ar * 64 + kt + lk);
        As[lk + 0][lm] = av.x; As[lk + 1][lm] = av.y;
        As[lk + 2][lm] = av.z; As[lk + 3][lm] = av.w;
        float4 bv = *(const float4*)(B + (size_t)(kt + lkb) * 128 + col0 + lnb);
        Bs[lkb][lnb + 0] = bv.x; Bs[lkb][lnb + 1] = bv.y;
        Bs[lkb][lnb + 2] = bv.z; Bs[lkb][lnb + 3] = bv.w;
        __syncthreads();
        #pragma unroll
        for (int k = 0; k < 16; k++) {
            float a[4], b[4];
            #pragma unroll
            for (int i = 0; i < 4; i++) a[i] = As[k][(ty << 2) + i];
            #pragma unroll
            for (int j = 0; j < 4; j++) b[j] = Bs[k][(tx << 2) + j];
            #pragma unroll
            for (int i = 0; i < 4; i++)
                #pragma unroll
                for (int j = 0; j < 4; j++) acc[i][j] = fmaf(a[i], b[j], acc[i][j]);
        }
        __syncthreads();
    }
    #pragma unroll
    for (int i = 0; i < 4; i++) {
        int r = row0 + (ty << 2) + i;
        if (r >= M) continue;
        int sn = srcs[r];
        const float* vp = V + (size_t)sn * 128;
        #pragma unroll
        for (int j = 0; j < 4; j++) {
            int c = col0 + (tx << 2) + j;
            float g = acc[i][j] + bias[c];
            g = 1.0f / (1.0f + expf(-g));
            float at = ATT[(size_t)r * 8 + (c >> 4)];
            WS[(size_t)r * 128 + c] = g * at * __ldg(vp + c);
        }
    }
}

// ---------------- contiguous segment sum: warp per node ---------------------
__global__ void segsum_kernel(const float* __restrict__ WS, const int* __restrict__ rowstart,
                              float* __restrict__ AGG, int N) {
    int warp = (blockIdx.x * blockDim.x + threadIdx.x) >> 5;
    int lane = threadIdx.x & 31;
    if (warp >= N) return;
    int s0 = rowstart[warp], s1 = rowstart[warp + 1];
    float4 acc = make_float4(0.f, 0.f, 0.f, 0.f);
    for (int i = s0; i < s1; i++) {
        float4 v = *(const float4*)(WS + (size_t)i * 128 + lane * 4);
        acc.x += v.x; acc.y += v.y; acc.z += v.z; acc.w += v.w;
    }
    *(float4*)(AGG + (size_t)warp * 128 + lane * 4) = acc;
}

// ---------------- launch ----------------------------------------------------
extern "C" void kernel_launch(void* const* d_in, const int* in_sizes, int n_in,
                              void* d_out, int out_size) {
    const float* x      = (const float*)d_in[0];
    const float* ea     = (const float*)d_in[1];
    const float* gamma  = (const float*)d_in[2];
    const float* beta   = (const float*)d_in[3];
    const float* Wq     = (const float*)d_in[4];
    const float* Wk     = (const float*)d_in[5];
    const float* Wv     = (const float*)d_in[6];
    const float* Wo     = (const float*)d_in[7];
    const float* bo     = (const float*)d_in[8];
    const float* ea_w1  = (const float*)d_in[9];
    const float* ea_b1  = (const float*)d_in[10];
    const float* ea_w2  = (const float*)d_in[11];
    const float* ea_b2  = (const float*)d_in[12];
    const float* eg_w1  = (const float*)d_in[13];
    const float* eg_b1  = (const float*)d_in[14];
    const float* eg_w2  = (const float*)d_in[15];
    const float* eg_b2  = (const float*)d_in[16];
    const float* ln1_g  = (const float*)d_in[17];
    const float* ln1_b  = (const float*)d_in[18];
    const float* ln2_g  = (const float*)d_in[19];
    const float* ln2_b  = (const float*)d_in[20];
    const float* ffn_w1 = (const float*)d_in[21];
    const float* ffn_b1 = (const float*)d_in[22];
    const float* ffn_w2 = (const float*)d_in[23];
    const float* ffn_b2 = (const float*)d_in[24];
    const int*   ei     = (const int*)d_in[25];

    int N = in_sizes[0] / 128;
    int E = in_sizes[25] / 2;

    float *pXN, *pQ, *pK, *pV, *pAGG, *pXMID, *pFFNH, *pHE, *pLOG, *pATT, *pWS;
    int *pPerm, *pSrc, *pDst, *pCnt, *pRow, *pCur, *pBsum, *pBsumex;
    cudaGetSymbolAddress((void**)&pXN, g_XN);
    cudaGetSymbolAddress((void**)&pQ, g_Q);
    cudaGetSymbolAddress((void**)&pK, g_K);
    cudaGetSymbolAddress((void**)&pV, g_V);
    cudaGetSymbolAddress((void**)&pAGG, g_AGG);
    cudaGetSymbolAddress((void**)&pXMID, g_XMID);
    cudaGetSymbolAddress((void**)&pFFNH, g_FFNH);
    cudaGetSymbolAddress((void**)&pHE, g_HE);
    cudaGetSymbolAddress((void**)&pLOG, g_LOG);
    cudaGetSymbolAddress((void**)&pATT, g_ATT);
    cudaGetSymbolAddress((void**)&pWS, g_WS);
    cudaGetSymbolAddress((void**)&pPerm, g_perm);
    cudaGetSymbolAddress((void**)&pSrc, g_srcs);
    cudaGetSymbolAddress((void**)&pDst, g_dsts);
    cudaGetSymbolAddress((void**)&pCnt, g_cnt);
    cudaGetSymbolAddress((void**)&pRow, g_rowstart);
    cudaGetSymbolAddress((void**)&pCur, g_cursor);
    cudaGetSymbolAddress((void**)&pBsum, g_bsum);
    cudaGetSymbolAddress((void**)&pBsumex, g_bsumex);

    int nb = (N + 255) / 256;

    // ---- edge sort by dst ----
    cudaMemsetAsync(pCnt, 0, (size_t)N * sizeof(int));
    hist_kernel<<<(E + 255) / 256, 256>>>(ei, pCnt, E);
    scan1_kernel<<<nb, 256>>>(pCnt, pRow, pBsum, N);
    scan2_kernel<<<1, 256>>>(pBsum, pBsumex, nb);
    scan3_kernel<<<nb, 256>>>(pRow, pCur, pBsumex, N, E);
    scatter_kernel<<<(E + 255) / 256, 256>>>(ei, pCur, pPerm, pSrc, pDst, E);

    // ---- node pre-attention ----
    int lnBlocks = (N * 32 + 255) / 256;
    ln_kernel<<<lnBlocks, 256>>>(x, ln1_g, ln1_b, pXN, N);
    dim3 g128(2, (N + 63) / 64);
    gemm_kernel<<<g128, 256>>>(pXN, Wq, nullptr, nullptr, nullptr, nullptr, pQ, N, 128, 128, 0, nullptr);
    gemm_kernel<<<g128, 256>>>(pXN, Wk, nullptr, nullptr, nullptr, nullptr, pK, N, 128, 128, 0, nullptr);
    gemm_kernel<<<g128, 256>>>(pXN, Wv, nullptr, nullptr, nullptr, nullptr, pV, N, 128, 128, 0, nullptr);

    // ---- edge attention ----
    dim3 ge64(1, (E + 63) / 64);
    // HA = gelu(EA[perm] @ ea_w1 + b1)
    gemm_kernel<<<ge64, 256>>>(ea, ea_w1, ea_b1, nullptr, nullptr, nullptr, pHE, E, 64, 32, 1, pPerm);
    logits_kernel<<<(E + 63) / 64, 256>>>(pHE, pSrc, pDst, ea_w2, ea_b2, pQ, pK, pLOG, E);
    softmax_kernel<<<(N * 32 + 255) / 256, 256>>>(pLOG, pRow, pATT, N);
    // HG = gelu(EA[perm] @ eg_w1 + b1)  (reuse HE buffer)
    gemm_kernel<<<ge64, 256>>>(ea, eg_w1, eg_b1, nullptr, nullptr, nullptr, pHE, E, 64, 32, 1, pPerm);
    dim3 gg(2, (E + 63) / 64);
    gate_gemm_kernel<<<gg, 256>>>(pHE, eg_w2, eg_b2, pV, pSrc, pATT, pWS, E);
    segsum_kernel<<<(N * 32 + 255) / 256, 256>>>(pWS, pRow, pAGG, N);

    // ---- node post-attention ----
    gemm_kernel<<<g128, 256>>>(pAGG, Wo, bo, x, gamma, beta, pXMID, N, 128, 128, 3, nullptr);
    ln_kernel<<<lnBlocks, 256>>>(pXMID, ln2_g, ln2_b, pXN, N);
    dim3 g256(4, (N + 63) / 64);
    gemm_kernel<<<g256, 256>>>(pXN, ffn_w1, ffn_b1, nullptr, nullptr, nullptr, pFFNH, N, 256, 128, 1, nullptr);
    gemm_kernel<<<g128, 256>>>(pFFNH, ffn_w2, ffn_b2, pXMID, nullptr, nullptr,
                               (float*)d_out, N, 128, 256, 2, nullptr);
}

// round 4
// speedup vs baseline: 1.3489x; 1.0652x over previous
#include <cuda_runtime.h>
#include <math.h>

#define NMAX 50000
#define EMAX 500000

// ---------------- static scratch ------------------------------------------
__device__ float g_XN[NMAX * 128];
__device__ float g_Q[NMAX * 128];
__device__ float g_K[NMAX * 128];
__device__ float g_V[NMAX * 128];
__device__ float g_AGG[NMAX * 128];
__device__ float g_XMID[NMAX * 128];
__device__ float g_FFNH[NMAX * 256];
__device__ float g_LOG[EMAX * 8];
__device__ float g_ATT[EMAX * 8];
__device__ float g_WS[EMAX * 128];
__device__ int   g_perm[EMAX];
__device__ int   g_srcs[EMAX];
__device__ int   g_dsts[EMAX];
__device__ int   g_cnt[NMAX];
__device__ int   g_rowstart[NMAX + 1];
__device__ int   g_cursor[NMAX];
__device__ int   g_bsum[256];
__device__ int   g_bsumex[256];

__device__ __forceinline__ float gelu_f(float x) {
    return 0.5f * x * (1.0f + erff(x * 0.70710678118654752f));
}
__device__ __forceinline__ float sigmoid_f(float x) {
    return 1.0f / (1.0f + expf(-x));
}

// ---------------- LayerNorm: one warp per row of 128 ------------------------
__global__ void ln_kernel(const float* __restrict__ X, const float* __restrict__ G,
                          const float* __restrict__ B, float* __restrict__ O, int Nrows) {
    int warp = (blockIdx.x * blockDim.x + threadIdx.x) >> 5;
    int lane = threadIdx.x & 31;
    if (warp >= Nrows) return;
    const float* xp = X + (size_t)warp * 128;
    float4 v = *(const float4*)(xp + lane * 4);
    float s = v.x + v.y + v.z + v.w;
    #pragma unroll
    for (int o = 16; o; o >>= 1) s += __shfl_xor_sync(0xffffffffu, s, o);
    float mean = s * (1.0f / 128.0f);
    float d0 = v.x - mean, d1 = v.y - mean, d2 = v.z - mean, d3 = v.w - mean;
    float ss = d0 * d0 + d1 * d1 + d2 * d2 + d3 * d3;
    #pragma unroll
    for (int o = 16; o; o >>= 1) ss += __shfl_xor_sync(0xffffffffu, ss, o);
    float inv = rsqrtf(ss * (1.0f / 128.0f) + 1e-5f);
    float* op = O + (size_t)warp * 128;
    int c = lane * 4;
    op[c + 0] = d0 * inv * G[c + 0] + B[c + 0];
    op[c + 1] = d1 * inv * G[c + 1] + B[c + 1];
    op[c + 2] = d2 * inv * G[c + 2] + B[c + 2];
    op[c + 3] = d3 * inv * G[c + 3] + B[c + 3];
}

// ---------------- fp32 GEMM, 128x128x16 tiles, 8x8/thread, fused epilogues --
// mode 0: C = A@B + bias
// mode 1: C = gelu(A@B + bias)
// mode 2: C = res + A@B + bias
// mode 3: C = res + gam*(A@B + bias) + bet
// Requirements: K % 16 == 0, N % 128 == 0 (true for all call sites).
__global__ void gemm128_kernel(const float* __restrict__ A, const float* __restrict__ B,
                               const float* __restrict__ bias, const float* __restrict__ res,
                               const float* __restrict__ gam, const float* __restrict__ bet,
                               float* __restrict__ C, int M, int N, int K, int mode) {
    __shared__ float As[16][132];
    __shared__ float Bs[16][132];
    const int tid = threadIdx.x;
    const int tx = tid & 15, ty = tid >> 4;
    const int row0 = blockIdx.y * 128, col0 = blockIdx.x * 128;
    float acc[8][8] = {};
    const int arow = tid >> 2, akq = (tid & 3) << 2;
    const int bkr = tid >> 5, bc = (tid & 31) << 2;
    for (int kt = 0; kt < K; kt += 16) {
        #pragma unroll
        for (int p = 0; p < 2; p++) {
            int rr = arow + p * 64;
            int r = row0 + rr;
            float4 av = make_float4(0.f, 0.f, 0.f, 0.f);
            if (r < M) av = *(const float4*)(A + (size_t)r * K + kt + akq);
            As[akq + 0][rr] = av.x;
            As[akq + 1][rr] = av.y;
            As[akq + 2][rr] = av.z;
            As[akq + 3][rr] = av.w;
            float4 bv = *(const float4*)(B + (size_t)(kt + bkr + p * 8) * N + col0 + bc);
            *(float4*)&Bs[bkr + p * 8][bc] = bv;
        }
        __syncthreads();
        #pragma unroll
        for (int k = 0; k < 16; k++) {
            float a[8], b[8];
            *(float4*)(a + 0) = *(const float4*)&As[k][ty * 8];
            *(float4*)(a + 4) = *(const float4*)&As[k][ty * 8 + 4];
            *(float4*)(b + 0) = *(const float4*)&Bs[k][tx * 4];
            *(float4*)(b + 4) = *(const float4*)&Bs[k][64 + tx * 4];
            #pragma unroll
            for (int i = 0; i < 8; i++)
                #pragma unroll
                for (int j = 0; j < 8; j++) acc[i][j] = fmaf(a[i], b[j], acc[i][j]);
        }
        __syncthreads();
    }
    // epilogue: cols j 0..3 -> col0+tx*4+j ; j 4..7 -> col0+64+tx*4+(j-4)
    const int c0 = col0 + tx * 4;
    float4 bi0 = make_float4(0.f, 0.f, 0.f, 0.f), bi1 = bi0;
    if (bias) {
        bi0 = *(const float4*)(bias + c0);
        bi1 = *(const float4*)(bias + c0 + 64);
    }
    #pragma unroll
    for (int i = 0; i < 8; i++) {
        int r = row0 + ty * 8 + i;
        if (r >= M) continue;
        size_t idx0 = (size_t)r * N + c0;
        float4 v0, v1;
        v0.x = acc[i][0] + bi0.x; v0.y = acc[i][1] + bi0.y;
        v0.z = acc[i][2] + bi0.z; v0.w = acc[i][3] + bi0.w;
        v1.x = acc[i][4] + bi1.x; v1.y = acc[i][5] + bi1.y;
        v1.z = acc[i][6] + bi1.z; v1.w = acc[i][7] + bi1.w;
        if (mode == 1) {
            v0.x = gelu_f(v0.x); v0.y = gelu_f(v0.y); v0.z = gelu_f(v0.z); v0.w = gelu_f(v0.w);
            v1.x = gelu_f(v1.x); v1.y = gelu_f(v1.y); v1.z = gelu_f(v1.z); v1.w = gelu_f(v1.w);
        } else if (mode == 2) {
            float4 r0 = *(const float4*)(res + idx0);
            float4 r1 = *(const float4*)(res + idx0 + 64);
            v0.x += r0.x; v0.y += r0.y; v0.z += r0.z; v0.w += r0.w;
            v1.x += r1.x; v1.y += r1.y; v1.z += r1.z; v1.w += r1.w;
        } else if (mode == 3) {
            float4 r0 = *(const float4*)(res + idx0);
            float4 r1 = *(const float4*)(res + idx0 + 64);
            float4 gm0 = *(const float4*)(gam + idx0);
            float4 gm1 = *(const float4*)(gam + idx0 + 64);
            float4 bt0 = *(const float4*)(bet + idx0);
            float4 bt1 = *(const float4*)(bet + idx0 + 64);
            v0.x = r0.x + gm0.x * v0.x + bt0.x; v0.y = r0.y + gm0.y * v0.y + bt0.y;
            v0.z = r0.z + gm0.z * v0.z + bt0.z; v0.w = r0.w + gm0.w * v0.w + bt0.w;
            v1.x = r1.x + gm1.x * v1.x + bt1.x; v1.y = r1.y + gm1.y * v1.y + bt1.y;
            v1.z = r1.z + gm1.z * v1.z + bt1.z; v1.w = r1.w + gm1.w * v1.w + bt1.w;
        }
        *(float4*)(C + idx0) = v0;
        *(float4*)(C + idx0 + 64) = v1;
    }
}

// ---------------- counting sort of edges by dst -----------------------------
__global__ void hist_kernel(const int* __restrict__ EI, int* __restrict__ cnt, int E) {
    int e = blockIdx.x * 256 + threadIdx.x;
    if (e < E) atomicAdd(&cnt[EI[E + e]], 1);
}

__global__ void scan1_kernel(const int* __restrict__ cnt, int* __restrict__ excl,
                             int* __restrict__ bsum, int N) {
    __shared__ int sm[256];
    int t = threadIdx.x, i = blockIdx.x * 256 + t;
    int v = (i < N) ? cnt[i] : 0;
    sm[t] = v; __syncthreads();
    for (int o = 1; o < 256; o <<= 1) {
        int a = (t >= o) ? sm[t - o] : 0;
        __syncthreads();
        sm[t] += a;
        __syncthreads();
    }
    if (i < N) excl[i] = sm[t] - v;
    if (t == 255) bsum[blockIdx.x] = sm[255];
}

__global__ void scan2_kernel(const int* __restrict__ bsum, int* __restrict__ bsumex, int nb) {
    __shared__ int sm[256];
    int t = threadIdx.x;
    int v = (t < nb) ? bsum[t] : 0;
    sm[t] = v; __syncthreads();
    for (int o = 1; o < 256; o <<= 1) {
        int a = (t >= o) ? sm[t - o] : 0;
        __syncthreads();
        sm[t] += a;
        __syncthreads();
    }
    bsumex[t] = sm[t] - v;
}

__global__ void scan3_kernel(int* __restrict__ rowstart, int* __restrict__ cursor,
                             const int* __restrict__ bsumex, int N, int E) {
    int i = blockIdx.x * 256 + threadIdx.x;
    if (i < N) {
        int v = rowstart[i] + bsumex[blockIdx.x];
        rowstart[i] = v;
        cursor[i] = v;
        if (i == N - 1) rowstart[N] = E;
    }
}

__global__ void scatter_kernel(const int* __restrict__ EI, int* __restrict__ cursor,
                               int* __restrict__ perm, int* __restrict__ srcs,
                               int* __restrict__ dsts, int E) {
    int e = blockIdx.x * 256 + threadIdx.x;
    if (e >= E) return;
    int d = EI[E + e];
    int pos = atomicAdd(&cursor[d], 1);
    perm[pos] = e;
    srcs[pos] = EI[e];
    dsts[pos] = d;
}

// ---------------- logits (sorted order), fused ea-MLP -----------------------
// LOG[i,h] = (Q[dst[i],h,:].K[src[i],h,:])/4 + gelu(EA[perm[i]]@W1+B1)@W2 + B2
__global__ void logits_kernel(const float* __restrict__ EA, const int* __restrict__ perm,
                              const int* __restrict__ srcs, const int* __restrict__ dsts,
                              const float* __restrict__ W1, const float* __restrict__ B1,
                              const float* __restrict__ W2, const float* __restrict__ B2,
                              const float* __restrict__ Q, const float* __restrict__ Kk,
                              float* __restrict__ LOG, int E) {
    __shared__ float attr[64][33];
    __shared__ float w1s[32][65];
    __shared__ float ha[64][65];
    __shared__ float w2s[64][9];
    __shared__ float b2s[8];
    __shared__ int s_src[64], s_dst[64], s_perm[64];
    const int tid = threadIdx.x;
    const int e0 = blockIdx.x * 64;
    if (tid < 64) {
        int ge = e0 + tid;
        bool ok = ge < E;
        s_perm[tid] = ok ? perm[ge] : 0;
        s_src[tid] = ok ? srcs[ge] : 0;
        s_dst[tid] = ok ? dsts[ge] : 0;
    }
    for (int i = tid; i < 32 * 64; i += 256) w1s[i >> 6][i & 63] = W1[i];
    for (int i = tid; i < 64 * 8; i += 256) w2s[i >> 3][i & 7] = W2[i];
    if (tid < 8) b2s[tid] = B2[tid];
    __syncthreads();
    for (int i = tid; i < 64 * 32; i += 256) {
        int e = i >> 5, f = i & 31;
        attr[e][f] = (e0 + e < E) ? EA[(size_t)s_perm[e] * 32 + f] : 0.0f;
    }
    __syncthreads();
    // hidden = gelu(attr @ W1 + B1): 64x64, 4x4 per thread
    {
        const int tx = tid & 15, ty = tid >> 4;
        float acc[4][4] = {};
        for (int k = 0; k < 32; k++) {
            float a[4], b[4];
            #pragma unroll
            for (int i = 0; i < 4; i++) a[i] = attr[(ty << 2) + i][k];
            #pragma unroll
            for (int j = 0; j < 4; j++) b[j] = w1s[k][(tx << 2) + j];
            #pragma unroll
            for (int i = 0; i < 4; i++)
                #pragma unroll
                for (int j = 0; j < 4; j++) acc[i][j] = fmaf(a[i], b[j], acc[i][j]);
        }
        #pragma unroll
        for (int i = 0; i < 4; i++)
            #pragma unroll
            for (int j = 0; j < 4; j++)
                ha[(ty << 2) + i][(tx << 2) + j] =
                    gelu_f(acc[i][j] + __ldg(B1 + (tx << 2) + j));
    }
    __syncthreads();
    for (int i = tid; i < 512; i += 256) {
        int e = i >> 3, h = i & 7;
        int ge = e0 + e;
        if (ge >= E) continue;
        const float* qp = Q + (size_t)s_dst[e] * 128 + h * 16;
        const float* kp = Kk + (size_t)s_src[e] * 128 + h * 16;
        float lg = 0.0f;
        #pragma unroll
        for (int d = 0; d < 16; d += 4) {
            float4 qv = *(const float4*)(qp + d);
            float4 kv = *(const float4*)(kp + d);
            lg += qv.x * kv.x + qv.y * kv.y + qv.z * kv.z + qv.w * kv.w;
        }
        lg *= 0.25f;
        float a = b2s[h];
        #pragma unroll 8
        for (int k = 0; k < 64; k++) a = fmaf(ha[e][k], w2s[k][h], a);
        LOG[(size_t)ge * 8 + h] = lg + a;
    }
}

// ---------------- per-node softmax (warp/node, max clamped at 0) ------------
__global__ void softmax_kernel(const float* __restrict__ LOG, const int* __restrict__ rowstart,
                               float* __restrict__ ATT, int N) {
    int warp = (blockIdx.x * blockDim.x + threadIdx.x) >> 5;
    int lane = threadIdx.x & 31;
    if (warp >= N) return;
    int s0 = rowstart[warp], s1 = rowstart[warp + 1];
    int eo = lane >> 3, h = lane & 7;
    float m = 0.0f;  // include_self max-with-0
    for (int i = s0 + eo; i < s1; i += 4) m = fmaxf(m, LOG[(size_t)i * 8 + h]);
    m = fmaxf(m, __shfl_xor_sync(0xffffffffu, m, 8));
    m = fmaxf(m, __shfl_xor_sync(0xffffffffu, m, 16));
    float s = 0.0f;
    for (int i = s0 + eo; i < s1; i += 4) s += expf(LOG[(size_t)i * 8 + h] - m);
    s += __shfl_xor_sync(0xffffffffu, s, 8);
    s += __shfl_xor_sync(0xffffffffu, s, 16);
    float inv = 1.0f / (s + 1e-10f);
    for (int i = s0 + eo; i < s1; i += 4)
        ATT[(size_t)i * 8 + h] = expf(LOG[(size_t)i * 8 + h] - m) * inv;
}

// ---------------- fused gate: WS = sigmoid(gelu(EA@W1+b1)@W2+b2)*att*V[src] -
// 64 edges / block, 256 threads; gate GEMM done in two 64-col halves.
__global__ void gate_agg_kernel(const float* __restrict__ EA, const int* __restrict__ perm,
                                const int* __restrict__ srcs,
                                const float* __restrict__ W1, const float* __restrict__ B1,
                                const float* __restrict__ W2, const float* __restrict__ B2,
                                const float* __restrict__ V, const float* __restrict__ ATT,
                                float* __restrict__ WS, int E) {
    __shared__ float hg[64][65];
    __shared__ float buf[64 * 68];   // stage1: attr[64][33] + w1[32][65]; stage2: w2half[64][68]
    __shared__ int s_src[64], s_perm[64];
    const int tid = threadIdx.x;
    const int tx = tid & 15, ty = tid >> 4;
    const int e0 = blockIdx.x * 64;
    float* attr = buf;               // [64][33]
    float* w1s = buf + 64 * 33;      // [32][65]
    if (tid < 64) {
        int ge = e0 + tid;
        bool ok = ge < E;
        s_perm[tid] = ok ? perm[ge] : 0;
        s_src[tid] = ok ? srcs[ge] : 0;
    }
    for (int i = tid; i < 32 * 64; i += 256) w1s[(i >> 6) * 65 + (i & 63)] = W1[i];
    __syncthreads();
    for (int i = tid; i < 64 * 32; i += 256) {
        int e = i >> 5, f = i & 31;
        attr[e * 33 + f] = (e0 + e < E) ? EA[(size_t)s_perm[e] * 32 + f] : 0.0f;
    }
    __syncthreads();
    // hidden: hg = gelu(attr @ W1 + B1), 4x4 per thread
    {
        float acc[4][4] = {};
        for (int k = 0; k < 32; k++) {
            float a[4], b[4];
            #pragma unroll
            for (int i = 0; i < 4; i++) a[i] = attr[((ty << 2) + i) * 33 + k];
            #pragma unroll
            for (int j = 0; j < 4; j++) b[j] = w1s[k * 65 + (tx << 2) + j];
            #pragma unroll
            for (int i = 0; i < 4; i++)
                #pragma unroll
                for (int j = 0; j < 4; j++) acc[i][j] = fmaf(a[i], b[j], acc[i][j]);
        }
        #pragma unroll
        for (int i = 0; i < 4; i++)
            #pragma unroll
            for (int j = 0; j < 4; j++)
                hg[(ty << 2) + i][(tx << 2) + j] =
                    gelu_f(acc[i][j] + __ldg(B1 + (tx << 2) + j));
    }
    // gate GEMM in two 64-col halves
    #pragma unroll
    for (int half = 0; half < 2; half++) {
        __syncthreads();  // protect buf overwrite
        for (int i = tid; i < 64 * 64; i += 256) {
            int k = i >> 6, c = i & 63;
            buf[k * 68 + c] = W2[k * 128 + half * 64 + c];
        }
        __syncthreads();
        float acc[4][4] = {};
        #pragma unroll 16
        for (int k = 0; k < 64; k++) {
            float a[4], b[4];
            #pragma unroll
            for (int i = 0; i < 4; i++) a[i] = hg[(ty << 2) + i][k];
            #pragma unroll
            for (int j = 0; j < 4; j++) b[j] = buf[k * 68 + (tx << 2) + j];
            #pragma unroll
            for (int i = 0; i < 4; i++)
                #pragma unroll
                for (int j = 0; j < 4; j++) acc[i][j] = fmaf(a[i], b[j], acc[i][j]);
        }
        int col = half * 64 + (tx << 2);
        float4 b2v = *(const float4*)(B2 + col);
        int head = col >> 4;
        #pragma unroll
        for (int i = 0; i < 4; i++) {
            int le = (ty << 2) + i;
            int ge = e0 + le;
            if (ge >= E) continue;
            float at = __ldg(ATT + (size_t)ge * 8 + head);
            float4 vv = *(const float4*)(V + (size_t)s_src[le] * 128 + col);
            float4 o;
            o.x = sigmoid_f(acc[i][0] + b2v.x) * at * vv.x;
            o.y = sigmoid_f(acc[i][1] + b2v.y) * at * vv.y;
            o.z = sigmoid_f(acc[i][2] + b2v.z) * at * vv.z;
            o.w = sigmoid_f(acc[i][3] + b2v.w) * at * vv.w;
            *(float4*)(WS + (size_t)ge * 128 + col) = o;
        }
    }
}

// ---------------- contiguous segment sum: warp per node ---------------------
__global__ void segsum_kernel(const float* __restrict__ WS, const int* __restrict__ rowstart,
                              float* __restrict__ AGG, int N) {
    int warp = (blockIdx.x * blockDim.x + threadIdx.x) >> 5;
    int lane = threadIdx.x & 31;
    if (warp >= N) return;
    int s0 = rowstart[warp], s1 = rowstart[warp + 1];
    float4 acc = make_float4(0.f, 0.f, 0.f, 0.f);
    for (int i = s0; i < s1; i++) {
        float4 v = *(const float4*)(WS + (size_t)i * 128 + lane * 4);
        acc.x += v.x; acc.y += v.y; acc.z += v.z; acc.w += v.w;
    }
    *(float4*)(AGG + (size_t)warp * 128 + lane * 4) = acc;
}

// ---------------- launch ----------------------------------------------------
extern "C" void kernel_launch(void* const* d_in, const int* in_sizes, int n_in,
                              void* d_out, int out_size) {
    const float* x      = (const float*)d_in[0];
    const float* ea     = (const float*)d_in[1];
    const float* gamma  = (const float*)d_in[2];
    const float* beta   = (const float*)d_in[3];
    const float* Wq     = (const float*)d_in[4];
    const float* Wk     = (const float*)d_in[5];
    const float* Wv     = (const float*)d_in[6];
    const float* Wo     = (const float*)d_in[7];
    const float* bo     = (const float*)d_in[8];
    const float* ea_w1  = (const float*)d_in[9];
    const float* ea_b1  = (const float*)d_in[10];
    const float* ea_w2  = (const float*)d_in[11];
    const float* ea_b2  = (const float*)d_in[12];
    const float* eg_w1  = (const float*)d_in[13];
    const float* eg_b1  = (const float*)d_in[14];
    const float* eg_w2  = (const float*)d_in[15];
    const float* eg_b2  = (const float*)d_in[16];
    const float* ln1_g  = (const float*)d_in[17];
    const float* ln1_b  = (const float*)d_in[18];
    const float* ln2_g  = (const float*)d_in[19];
    const float* ln2_b  = (const float*)d_in[20];
    const float* ffn_w1 = (const float*)d_in[21];
    const float* ffn_b1 = (const float*)d_in[22];
    const float* ffn_w2 = (const float*)d_in[23];
    const float* ffn_b2 = (const float*)d_in[24];
    const int*   ei     = (const int*)d_in[25];

    int N = in_sizes[0] / 128;
    int E = in_sizes[25] / 2;

    float *pXN, *pQ, *pK, *pV, *pAGG, *pXMID, *pFFNH, *pLOG, *pATT, *pWS;
    int *pPerm, *pSrc, *pDst, *pCnt, *pRow, *pCur, *pBsum, *pBsumex;
    cudaGetSymbolAddress((void**)&pXN, g_XN);
    cudaGetSymbolAddress((void**)&pQ, g_Q);
    cudaGetSymbolAddress((void**)&pK, g_K);
    cudaGetSymbolAddress((void**)&pV, g_V);
    cudaGetSymbolAddress((void**)&pAGG, g_AGG);
    cudaGetSymbolAddress((void**)&pXMID, g_XMID);
    cudaGetSymbolAddress((void**)&pFFNH, g_FFNH);
    cudaGetSymbolAddress((void**)&pLOG, g_LOG);
    cudaGetSymbolAddress((void**)&pATT, g_ATT);
    cudaGetSymbolAddress((void**)&pWS, g_WS);
    cudaGetSymbolAddress((void**)&pPerm, g_perm);
    cudaGetSymbolAddress((void**)&pSrc, g_srcs);
    cudaGetSymbolAddress((void**)&pDst, g_dsts);
    cudaGetSymbolAddress((void**)&pCnt, g_cnt);
    cudaGetSymbolAddress((void**)&pRow, g_rowstart);
    cudaGetSymbolAddress((void**)&pCur, g_cursor);
    cudaGetSymbolAddress((void**)&pBsum, g_bsum);
    cudaGetSymbolAddress((void**)&pBsumex, g_bsumex);

    int nb = (N + 255) / 256;

    // ---- edge sort by dst ----
    cudaMemsetAsync(pCnt, 0, (size_t)N * sizeof(int));
    hist_kernel<<<(E + 255) / 256, 256>>>(ei, pCnt, E);
    scan1_kernel<<<nb, 256>>>(pCnt, pRow, pBsum, N);
    scan2_kernel<<<1, 256>>>(pBsum, pBsumex, nb);
    scan3_kernel<<<nb, 256>>>(pRow, pCur, pBsumex, N, E);
    scatter_kernel<<<(E + 255) / 256, 256>>>(ei, pCur, pPerm, pSrc, pDst, E);

    // ---- node pre-attention ----
    int lnBlocks = (N * 32 + 255) / 256;
    ln_kernel<<<lnBlocks, 256>>>(x, ln1_g, ln1_b, pXN, N);
    dim3 gn(1, (N + 127) / 128);
    gemm128_kernel<<<gn, 256>>>(pXN, Wq, nullptr, nullptr, nullptr, nullptr, pQ, N, 128, 128, 0);
    gemm128_kernel<<<gn, 256>>>(pXN, Wk, nullptr, nullptr, nullptr, nullptr, pK, N, 128, 128, 0);
    gemm128_kernel<<<gn, 256>>>(pXN, Wv, nullptr, nullptr, nullptr, nullptr, pV, N, 128, 128, 0);

    // ---- edge attention ----
    logits_kernel<<<(E + 63) / 64, 256>>>(ea, pPerm, pSrc, pDst, ea_w1, ea_b1, ea_w2, ea_b2,
                                          pQ, pK, pLOG, E);
    softmax_kernel<<<(N * 32 + 255) / 256, 256>>>(pLOG, pRow, pATT, N);
    gate_agg_kernel<<<(E + 63) / 64, 256>>>(ea, pPerm, pSrc, eg_w1, eg_b1, eg_w2, eg_b2,
                                            pV, pATT, pWS, E);
    segsum_kernel<<<(N * 32 + 255) / 256, 256>>>(pWS, pRow, pAGG, N);

    // ---- node post-attention ----
    gemm128_kernel<<<gn, 256>>>(pAGG, Wo, bo, x, gamma, beta, pXMID, N, 128, 128, 3);
    ln_kernel<<<lnBlocks, 256>>>(pXMID, ln2_g, ln2_b, pXN, N);
    dim3 gn2(2, (N + 127) / 128);
    gemm128_kernel<<<gn2, 256>>>(pXN, ffn_w1, ffn_b1, nullptr, nullptr, nullptr, pFFNH, N, 256, 128, 1);
    gemm128_kernel<<<gn, 256>>>(pFFNH, ffn_w2, ffn_b2, pXMID, nullptr, nullptr,
                                (float*)d_out, N, 128, 256, 2);
}

// round 5
// speedup vs baseline: 1.4912x; 1.1055x over previous
#include <cuda_runtime.h>
#include <math.h>

#define NMAX 50000
#define EMAX 500000

// ---------------- static scratch ------------------------------------------
__device__ float g_XN[NMAX * 128];
__device__ float g_Q[NMAX * 128];
__device__ float g_K[NMAX * 128];
__device__ float g_V[NMAX * 128];
__device__ float g_AGG[NMAX * 128];
__device__ float g_XMID[NMAX * 128];
__device__ float g_FFNH[NMAX * 256];
__device__ float g_HE[EMAX * 64];
__device__ float g_LOG[EMAX * 8];
__device__ float g_ATT[EMAX * 8];
__device__ float g_WS[EMAX * 128];
__device__ int   g_perm[EMAX];
__device__ int   g_srcs[EMAX];
__device__ int   g_dsts[EMAX];
__device__ int   g_cnt[NMAX];
__device__ int   g_rowstart[NMAX + 1];
__device__ int   g_cursor[NMAX];
__device__ int   g_bsum[256];
__device__ int   g_bsumex[256];

__device__ __forceinline__ float gelu_f(float x) {
    return 0.5f * x * (1.0f + erff(x * 0.70710678118654752f));
}
__device__ __forceinline__ float sigmoid_f(float x) {
    return 1.0f / (1.0f + expf(-x));
}
__device__ __forceinline__ float to_tf32(float x) {
    float r;
    asm("cvt.rna.tf32.f32 %0, %1;" : "=f"(r) : "f"(x));
    return r;
}

// ---------------- LayerNorm -------------------------------------------------
__global__ void ln_kernel(const float* __restrict__ X, const float* __restrict__ G,
                          const float* __restrict__ B, float* __restrict__ O, int Nrows) {
    int warp = (blockIdx.x * blockDim.x + threadIdx.x) >> 5;
    int lane = threadIdx.x & 31;
    if (warp >= Nrows) return;
    const float* xp = X + (size_t)warp * 128;
    float4 v = *(const float4*)(xp + lane * 4);
    float s = v.x + v.y + v.z + v.w;
    #pragma unroll
    for (int o = 16; o; o >>= 1) s += __shfl_xor_sync(0xffffffffu, s, o);
    float mean = s * (1.0f / 128.0f);
    float d0 = v.x - mean, d1 = v.y - mean, d2 = v.z - mean, d3 = v.w - mean;
    float ss = d0 * d0 + d1 * d1 + d2 * d2 + d3 * d3;
    #pragma unroll
    for (int o = 16; o; o >>= 1) ss += __shfl_xor_sync(0xffffffffu, ss, o);
    float inv = rsqrtf(ss * (1.0f / 128.0f) + 1e-5f);
    float* op = O + (size_t)warp * 128;
    int c = lane * 4;
    op[c + 0] = d0 * inv * G[c + 0] + B[c + 0];
    op[c + 1] = d1 * inv * G[c + 1] + B[c + 1];
    op[c + 2] = d2 * inv * G[c + 2] + B[c + 2];
    op[c + 3] = d3 * inv * G[c + 3] + B[c + 3];
}

// ---------------- tf32 tensor-core GEMM, BM=128 x BN, BK=32 -----------------
// modes: 0: +bias  1: gelu(+bias)  2: res+(+bias)  3: res+gam*(+bias)+bet
//        4: sigmoid(+bias)*ATT[row*8+col/16]*V[srcs[row]*128+col]
// rowidx: optional gather on A rows. Requires N % BN == 0, K % 32 == 0.
template <int BN, int NW>
__global__ void mma_gemm(const float* __restrict__ A, const float* __restrict__ B,
                         const float* __restrict__ bias, const float* __restrict__ res,
                         const float* __restrict__ gam, const float* __restrict__ bet,
                         const float* __restrict__ V, const int* __restrict__ srcs,
                         const float* __restrict__ ATT,
                         float* __restrict__ C, int M, int N, int K, int mode,
                         const int* __restrict__ rowidx) {
    constexpr int THREADS = NW * 32;
    constexpr int APAD = 132;
    constexpr int BPAD = BN + 4;
    __shared__ float As[32 * APAD];   // [k][m]
    __shared__ float Bs[32 * BPAD];   // [k][n]
    const int tid = threadIdx.x;
    const int lane = tid & 31, wid = tid >> 5;
    const int wm = wid & 1, wn = wid >> 1;  // 2 x (NW/2) warp grid
    const int row0 = blockIdx.y * 128, col0 = blockIdx.x * BN;
    const int warpM = wm * 64, warpN = wn * 32;
    float c[4][4][4];
    #pragma unroll
    for (int i = 0; i < 4; i++)
        #pragma unroll
        for (int j = 0; j < 4; j++)
            #pragma unroll
            for (int r = 0; r < 4; r++) c[i][j][r] = 0.0f;

    for (int kt = 0; kt < K; kt += 32) {
        // load A tile 128x32 -> As[k][m] (transposed, tf32-rounded)
        #pragma unroll
        for (int it = 0; it < 1024 / THREADS; it++) {
            int i = tid + it * THREADS;
            int r = i >> 3, kq = (i & 7) << 2;
            float4 av = make_float4(0.f, 0.f, 0.f, 0.f);
            int gr = row0 + r;
            if (gr < M) {
                int pr = rowidx ? rowidx[gr] : gr;
                av = *(const float4*)(A + (size_t)pr * K + kt + kq);
            }
            As[(kq + 0) * APAD + r] = to_tf32(av.x);
            As[(kq + 1) * APAD + r] = to_tf32(av.y);
            As[(kq + 2) * APAD + r] = to_tf32(av.z);
            As[(kq + 3) * APAD + r] = to_tf32(av.w);
        }
        // load B tile 32xBN -> Bs[k][n]
        #pragma unroll
        for (int it = 0; it < (32 * BN / 4) / THREADS; it++) {
            int i = tid + it * THREADS;
            int kr = i / (BN / 4), cq = (i % (BN / 4)) << 2;
            float4 bv = *(const float4*)(B + (size_t)(kt + kr) * N + col0 + cq);
            Bs[kr * BPAD + cq + 0] = to_tf32(bv.x);
            Bs[kr * BPAD + cq + 1] = to_tf32(bv.y);
            Bs[kr * BPAD + cq + 2] = to_tf32(bv.z);
            Bs[kr * BPAD + cq + 3] = to_tf32(bv.w);
        }
        __syncthreads();
        #pragma unroll
        for (int ks = 0; ks < 4; ks++) {
            int kb = ks * 8;
            // A fragments: 4 m-frags
            unsigned a[4][4];
            #pragma unroll
            for (int mf = 0; mf < 4; mf++) {
                int r = warpM + mf * 16 + (lane >> 2);
                int ck = kb + (lane & 3);
                a[mf][0] = __float_as_uint(As[ck * APAD + r]);
                a[mf][1] = __float_as_uint(As[ck * APAD + r + 8]);
                a[mf][2] = __float_as_uint(As[(ck + 4) * APAD + r]);
                a[mf][3] = __float_as_uint(As[(ck + 4) * APAD + r + 8]);
            }
            // B fragments: 4 n-frags
            unsigned b[4][2];
            #pragma unroll
            for (int nf = 0; nf < 4; nf++) {
                int n0 = warpN + nf * 8 + (lane >> 2);
                b[nf][0] = __float_as_uint(Bs[(kb + (lane & 3)) * BPAD + n0]);
                b[nf][1] = __float_as_uint(Bs[(kb + 4 + (lane & 3)) * BPAD + n0]);
            }
            #pragma unroll
            for (int mf = 0; mf < 4; mf++)
                #pragma unroll
                for (int nf = 0; nf < 4; nf++) {
                    asm volatile(
                        "mma.sync.aligned.m16n8k8.row.col.f32.tf32.tf32.f32 "
                        "{%0,%1,%2,%3}, {%4,%5,%6,%7}, {%8,%9}, {%0,%1,%2,%3};"
                        : "+f"(c[mf][nf][0]), "+f"(c[mf][nf][1]),
                          "+f"(c[mf][nf][2]), "+f"(c[mf][nf][3])
                        : "r"(a[mf][0]), "r"(a[mf][1]), "r"(a[mf][2]), "r"(a[mf][3]),
                          "r"(b[nf][0]), "r"(b[nf][1]));
                }
        }
        __syncthreads();
    }
    // epilogue: thread owns rows (lane>>2)+{0,8} per m-frag, cols 2*(lane&3)+{0,1} per n-frag
    #pragma unroll
    for (int mf = 0; mf < 4; mf++) {
        #pragma unroll
        for (int half = 0; half < 2; half++) {
            int r = row0 + warpM + mf * 16 + (lane >> 2) + half * 8;
            if (r >= M) continue;
            int sn = 0;
            if (mode == 4) sn = srcs[r];
            #pragma unroll
            for (int nf = 0; nf < 4; nf++) {
                int cc = col0 + warpN + nf * 8 + ((lane & 3) << 1);
                float v0 = c[mf][nf][half * 2 + 0];
                float v1 = c[mf][nf][half * 2 + 1];
                if (bias) { v0 += bias[cc]; v1 += bias[cc + 1]; }
                size_t idx = (size_t)r * N + cc;
                if (mode == 1) {
                    v0 = gelu_f(v0); v1 = gelu_f(v1);
                } else if (mode == 2) {
                    v0 += res[idx]; v1 += res[idx + 1];
                } else if (mode == 3) {
                    v0 = res[idx] + gam[idx] * v0 + bet[idx];
                    v1 = res[idx + 1] + gam[idx + 1] * v1 + bet[idx + 1];
                } else if (mode == 4) {
                    float at = __ldg(ATT + (size_t)r * 8 + (cc >> 4));
                    v0 = sigmoid_f(v0) * at * __ldg(V + (size_t)sn * 128 + cc);
                    v1 = sigmoid_f(v1) * at * __ldg(V + (size_t)sn * 128 + cc + 1);
                }
                float2 o = make_float2(v0, v1);
                *(float2*)(C + idx) = o;
            }
        }
    }
}

// ---------------- counting sort of edges by dst -----------------------------
__global__ void hist_kernel(const int* __restrict__ EI, int* __restrict__ cnt, int E) {
    int e = blockIdx.x * 256 + threadIdx.x;
    if (e < E) atomicAdd(&cnt[EI[E + e]], 1);
}

__global__ void scan1_kernel(const int* __restrict__ cnt, int* __restrict__ excl,
                             int* __restrict__ bsum, int N) {
    __shared__ int sm[256];
    int t = threadIdx.x, i = blockIdx.x * 256 + t;
    int v = (i < N) ? cnt[i] : 0;
    sm[t] = v; __syncthreads();
    for (int o = 1; o < 256; o <<= 1) {
        int a = (t >= o) ? sm[t - o] : 0;
        __syncthreads();
        sm[t] += a;
        __syncthreads();
    }
    if (i < N) excl[i] = sm[t] - v;
    if (t == 255) bsum[blockIdx.x] = sm[255];
}

__global__ void scan2_kernel(const int* __restrict__ bsum, int* __restrict__ bsumex, int nb) {
    __shared__ int sm[256];
    int t = threadIdx.x;
    int v = (t < nb) ? bsum[t] : 0;
    sm[t] = v; __syncthreads();
    for (int o = 1; o < 256; o <<= 1) {
        int a = (t >= o) ? sm[t - o] : 0;
        __syncthreads();
        sm[t] += a;
        __syncthreads();
    }
    bsumex[t] = sm[t] - v;
}

__global__ void scan3_kernel(int* __restrict__ rowstart, int* __restrict__ cursor,
                             const int* __restrict__ bsumex, int N, int E) {
    int i = blockIdx.x * 256 + threadIdx.x;
    if (i < N) {
        int v = rowstart[i] + bsumex[blockIdx.x];
        rowstart[i] = v;
        cursor[i] = v;
        if (i == N - 1) rowstart[N] = E;
    }
}

__global__ void scatter_kernel(const int* __restrict__ EI, int* __restrict__ cursor,
                               int* __restrict__ perm, int* __restrict__ srcs,
                               int* __restrict__ dsts, int E) {
    int e = blockIdx.x * 256 + threadIdx.x;
    if (e >= E) return;
    int d = EI[E + e];
    int pos = atomicAdd(&cursor[d], 1);
    perm[pos] = e;
    srcs[pos] = EI[e];
    dsts[pos] = d;
}

// ---------------- logits (sorted order), fused ea-MLP -----------------------
__global__ void logits_kernel(const float* __restrict__ EA, const int* __restrict__ perm,
                              const int* __restrict__ srcs, const int* __restrict__ dsts,
                              const float* __restrict__ W1, const float* __restrict__ B1,
                              const float* __restrict__ W2, const float* __restrict__ B2,
                              const float* __restrict__ Q, const float* __restrict__ Kk,
                              float* __restrict__ LOG, int E) {
    __shared__ float attr[64][33];
    __shared__ float w1s[32][65];
    __shared__ float ha[64][65];
    __shared__ float w2s[64][9];
    __shared__ float b2s[8];
    __shared__ int s_src[64], s_dst[64], s_perm[64];
    const int tid = threadIdx.x;
    const int e0 = blockIdx.x * 64;
    if (tid < 64) {
        int ge = e0 + tid;
        bool ok = ge < E;
        s_perm[tid] = ok ? perm[ge] : 0;
        s_src[tid] = ok ? srcs[ge] : 0;
        s_dst[tid] = ok ? dsts[ge] : 0;
    }
    for (int i = tid; i < 32 * 64; i += 256) w1s[i >> 6][i & 63] = W1[i];
    for (int i = tid; i < 64 * 8; i += 256) w2s[i >> 3][i & 7] = W2[i];
    if (tid < 8) b2s[tid] = B2[tid];
    __syncthreads();
    for (int i = tid; i < 64 * 32; i += 256) {
        int e = i >> 5, f = i & 31;
        attr[e][f] = (e0 + e < E) ? EA[(size_t)s_perm[e] * 32 + f] : 0.0f;
    }
    __syncthreads();
    {
        const int tx = tid & 15, ty = tid >> 4;
        float acc[4][4] = {};
        for (int k = 0; k < 32; k++) {
            float a[4], b[4];
            #pragma unroll
            for (int i = 0; i < 4; i++) a[i] = attr[(ty << 2) + i][k];
            #pragma unroll
            for (int j = 0; j < 4; j++) b[j] = w1s[k][(tx << 2) + j];
            #pragma unroll
            for (int i = 0; i < 4; i++)
                #pragma unroll
                for (int j = 0; j < 4; j++) acc[i][j] = fmaf(a[i], b[j], acc[i][j]);
        }
        #pragma unroll
        for (int i = 0; i < 4; i++)
            #pragma unroll
            for (int j = 0; j < 4; j++)
                ha[(ty << 2) + i][(tx << 2) + j] =
                    gelu_f(acc[i][j] + __ldg(B1 + (tx << 2) + j));
    }
    __syncthreads();
    for (int i = tid; i < 512; i += 256) {
        int e = i >> 3, h = i & 7;
        int ge = e0 + e;
        if (ge >= E) continue;
        const float* qp = Q + (size_t)s_dst[e] * 128 + h * 16;
        const float* kp = Kk + (size_t)s_src[e] * 128 + h * 16;
        float lg = 0.0f;
        #pragma unroll
        for (int d = 0; d < 16; d += 4) {
            float4 qv = *(const float4*)(qp + d);
            float4 kv = *(const float4*)(kp + d);
            lg += qv.x * kv.x + qv.y * kv.y + qv.z * kv.z + qv.w * kv.w;
        }
        lg *= 0.25f;
        float a = b2s[h];
        #pragma unroll 8
        for (int k = 0; k < 64; k++) a = fmaf(ha[e][k], w2s[k][h], a);
        LOG[(size_t)ge * 8 + h] = lg + a;
    }
}

// ---------------- per-node softmax ------------------------------------------
__global__ void softmax_kernel(const float* __restrict__ LOG, const int* __restrict__ rowstart,
                               float* __restrict__ ATT, int N) {
    int warp = (blockIdx.x * blockDim.x + threadIdx.x) >> 5;
    int lane = threadIdx.x & 31;
    if (warp >= N) return;
    int s0 = rowstart[warp], s1 = rowstart[warp + 1];
    int eo = lane >> 3, h = lane & 7;
    float m = 0.0f;
    for (int i = s0 + eo; i < s1; i += 4) m = fmaxf(m, LOG[(size_t)i * 8 + h]);
    m = fmaxf(m, __shfl_xor_sync(0xffffffffu, m, 8));
    m = fmaxf(m, __shfl_xor_sync(0xffffffffu, m, 16));
    float s = 0.0f;
    for (int i = s0 + eo; i < s1; i += 4) s += expf(LOG[(size_t)i * 8 + h] - m);
    s += __shfl_xor_sync(0xffffffffu, s, 8);
    s += __shfl_xor_sync(0xffffffffu, s, 16);
    float inv = 1.0f / (s + 1e-10f);
    for (int i = s0 + eo; i < s1; i += 4)
        ATT[(size_t)i * 8 + h] = expf(LOG[(size_t)i * 8 + h] - m) * inv;
}

// ---------------- contiguous segment sum ------------------------------------
__global__ void segsum_kernel(const float* __restrict__ WS, const int* __restrict__ rowstart,
                              float* __restrict__ AGG, int N) {
    int warp = (blockIdx.x * blockDim.x + threadIdx.x) >> 5;
    int lane = threadIdx.x & 31;
    if (warp >= N) return;
    int s0 = rowstart[warp], s1 = rowstart[warp + 1];
    float4 acc = make_float4(0.f, 0.f, 0.f, 0.f);
    for (int i = s0; i < s1; i++) {
        float4 v = *(const float4*)(WS + (size_t)i * 128 + lane * 4);
        acc.x += v.x; acc.y += v.y; acc.z += v.z; acc.w += v.w;
    }
    *(float4*)(AGG + (size_t)warp * 128 + lane * 4) = acc;
}

// ---------------- launch ----------------------------------------------------
extern "C" void kernel_launch(void* const* d_in, const int* in_sizes, int n_in,
                              void* d_out, int out_size) {
    const float* x      = (const float*)d_in[0];
    const float* ea     = (const float*)d_in[1];
    const float* gamma  = (const float*)d_in[2];
    const float* beta   = (const float*)d_in[3];
    const float* Wq     = (const float*)d_in[4];
    const float* Wk     = (const float*)d_in[5];
    const float* Wv     = (const float*)d_in[6];
    const float* Wo     = (const float*)d_in[7];
    const float* bo     = (const float*)d_in[8];
    const float* ea_w1  = (const float*)d_in[9];
    const float* ea_b1  = (const float*)d_in[10];
    const float* ea_w2  = (const float*)d_in[11];
    const float* ea_b2  = (const float*)d_in[12];
    const float* eg_w1  = (const float*)d_in[13];
    const float* eg_b1  = (const float*)d_in[14];
    const float* eg_w2  = (const float*)d_in[15];
    const float* eg_b2  = (const float*)d_in[16];
    const float* ln1_g  = (const float*)d_in[17];
    const float* ln1_b  = (const float*)d_in[18];
    const float* ln2_g  = (const float*)d_in[19];
    const float* ln2_b  = (const float*)d_in[20];
    const float* ffn_w1 = (const float*)d_in[21];
    const float* ffn_b1 = (const float*)d_in[22];
    const float* ffn_w2 = (const float*)d_in[23];
    const float* ffn_b2 = (const float*)d_in[24];
    const int*   ei     = (const int*)d_in[25];

    int N = in_sizes[0] / 128;
    int E = in_sizes[25] / 2;

    float *pXN, *pQ, *pK, *pV, *pAGG, *pXMID, *pFFNH, *pHE, *pLOG, *pATT, *pWS;
    int *pPerm, *pSrc, *pDst, *pCnt, *pRow, *pCur, *pBsum, *pBsumex;
    cudaGetSymbolAddress((void**)&pXN, g_XN);
    cudaGetSymbolAddress((void**)&pQ, g_Q);
    cudaGetSymbolAddress((void**)&pK, g_K);
    cudaGetSymbolAddress((void**)&pV, g_V);
    cudaGetSymbolAddress((void**)&pAGG, g_AGG);
    cudaGetSymbolAddress((void**)&pXMID, g_XMID);
    cudaGetSymbolAddress((void**)&pFFNH, g_FFNH);
    cudaGetSymbolAddress((void**)&pHE, g_HE);
    cudaGetSymbolAddress((void**)&pLOG, g_LOG);
    cudaGetSymbolAddress((void**)&pATT, g_ATT);
    cudaGetSymbolAddress((void**)&pWS, g_WS);
    cudaGetSymbolAddress((void**)&pPerm, g_perm);
    cudaGetSymbolAddress((void**)&pSrc, g_srcs);
    cudaGetSymbolAddress((void**)&pDst, g_dsts);
    cudaGetSymbolAddress((void**)&pCnt, g_cnt);
    cudaGetSymbolAddress((void**)&pRow, g_rowstart);
    cudaGetSymbolAddress((void**)&pCur, g_cursor);
    cudaGetSymbolAddress((void**)&pBsum, g_bsum);
    cudaGetSymbolAddress((void**)&pBsumex, g_bsumex);

    int nb = (N + 255) / 256;

    // ---- edge sort by dst ----
    cudaMemsetAsync(pCnt, 0, (size_t)N * sizeof(int));
    hist_kernel<<<(E + 255) / 256, 256>>>(ei, pCnt, E);
    scan1_kernel<<<nb, 256>>>(pCnt, pRow, pBsum, N);
    scan2_kernel<<<1, 256>>>(pBsum, pBsumex, nb);
    scan3_kernel<<<nb, 256>>>(pRow, pCur, pBsumex, N, E);
    scatter_kernel<<<(E + 255) / 256, 256>>>(ei, pCur, pPerm, pSrc, pDst, E);

    // ---- node pre-attention ----
    int lnBlocks = (N * 32 + 255) / 256;
    ln_kernel<<<lnBlocks, 256>>>(x, ln1_g, ln1_b, pXN, N);
    dim3 gn(1, (N + 127) / 128);
    mma_gemm<128, 8><<<gn, 256>>>(pXN, Wq, nullptr, nullptr, nullptr, nullptr,
                                  nullptr, nullptr, nullptr, pQ, N, 128, 128, 0, nullptr);
    mma_gemm<128, 8><<<gn, 256>>>(pXN, Wk, nullptr, nullptr, nullptr, nullptr,
                                  nullptr, nullptr, nullptr, pK, N, 128, 128, 0, nullptr);
    mma_gemm<128, 8><<<gn, 256>>>(pXN, Wv, nullptr, nullptr, nullptr, nullptr,
                                  nullptr, nullptr, nullptr, pV, N, 128, 128, 0, nullptr);

    // ---- edge attention ----
    logits_kernel<<<(E + 63) / 64, 256>>>(ea, pPerm, pSrc, pDst, ea_w1, ea_b1, ea_w2, ea_b2,
                                          pQ, pK, pLOG, E);
    softmax_kernel<<<(N * 32 + 255) / 256, 256>>>(pLOG, pRow, pATT, N);
    // HG = gelu(EA[perm] @ eg_w1 + b1): [E,64] via tf32 mma
    dim3 ge(1, (E + 127) / 128);
    mma_gemm<64, 4><<<ge, 128>>>(ea, eg_w1, eg_b1, nullptr, nullptr, nullptr,
                                 nullptr, nullptr, nullptr, pHE, E, 64, 32, 1, pPerm);
    // WS = sigmoid(HG @ eg_w2 + b2) * att * V[src]
    mma_gemm<128, 8><<<ge, 256>>>(pHE, eg_w2, eg_b2, nullptr, nullptr, nullptr,
                                  pV, pSrc, pATT, pWS, E, 128, 64, 4, nullptr);
    segsum_kernel<<<(N * 32 + 255) / 256, 256>>>(pWS, pRow, pAGG, N);

    // ---- node post-attention ----
    mma_gemm<128, 8><<<gn, 256>>>(pAGG, Wo, bo, x, gamma, beta,
                                  nullptr, nullptr, nullptr, pXMID, N, 128, 128, 3, nullptr);
    ln_kernel<<<lnBlocks, 256>>>(pXMID, ln2_g, ln2_b, pXN, N);
    dim3 gn2(2, (N + 127) / 128);
    mma_gemm<128, 8><<<gn2, 256>>>(pXN, ffn_w1, ffn_b1, nullptr, nullptr, nullptr,
                                   nullptr, nullptr, nullptr, pFFNH, N, 256, 128, 1, nullptr);
    mma_gemm<128, 8><<<gn, 256>>>(pFFNH, ffn_w2, ffn_b2, pXMID, nullptr, nullptr,
                                  nullptr, nullptr, nullptr, (float*)d_out, N, 128, 256, 2, nullptr);
}